// round 3
// baseline (speedup 1.0000x reference)
#include <cuda_runtime.h>

// DistTokenMix: out[b,i,d] = sum_j h[b,j,d] * alpha[spd[i,j], d]
// B=8, N=4096, D=64, NUM_BUCKETS=8

#define NN 4096
#define BB 8
#define DD 64
#define IT 32          // i-tile per block
#define JT 64          // j-tile staged in smem
#define TPB 256        // 64 d-lanes x 4 i-groups

// Packed buckets: word[ii*NN + j] holds buckets for i = 4*ii .. 4*ii+3 at column j,
// one byte each. 16 MB static device scratch (allocation-free rule).
__device__ unsigned int g_bpk[(NN / 4) * NN];

// ---------------------------------------------------------------------------
// Convert spd (int64 OR int32, detected at runtime) -> packed u32 buckets.
// ---------------------------------------------------------------------------
__global__ void __launch_bounds__(256) convert_spd_kernel(const unsigned int* __restrict__ spd_raw) {
    __shared__ int s_is64;
    if (threadIdx.x == 0) {
        // If spd is int64 (values < 8), every odd 32-bit word of the first 64 is 0.
        // If int32, odd words are uniform in [0,8): P(all zero) = 8^-32 ~ 0.
        unsigned int orv = 0;
#pragma unroll
        for (int t = 1; t < 64; t += 2) orv |= spd_raw[t];
        s_is64 = (orv == 0u) ? 1 : 0;
    }
    __syncthreads();
    const bool is64 = (s_is64 != 0);

    int idx = blockIdx.x * blockDim.x + threadIdx.x;   // over (NN/4)*NN
    int j  = idx & (NN - 1);
    int ii = idx >> 12;                                 // NN = 4096 = 2^12
    unsigned int w = 0;
#pragma unroll
    for (int c = 0; c < 4; ++c) {
        long long off = (long long)(4 * ii + c) * NN + j;
        unsigned int v = is64 ? spd_raw[off * 2]        // low word of int64 (little-endian)
                              : spd_raw[off];
        w |= (v & 7u) << (8 * c);
    }
    g_bpk[idx] = w;
}

// ---------------------------------------------------------------------------
// Packed fp32x2 FMA (FFMA2) — PTX-only path on sm_103a.
// ---------------------------------------------------------------------------
__device__ __forceinline__ float2 ffma2(float2 x, float2 y, float2 z) {
    float2 r;
    asm("fma.rn.f32x2 %0, %1, %2, %3;"
        : "=l"(*(unsigned long long*)&r)
        : "l"(*(unsigned long long*)&x),
          "l"(*(unsigned long long*)&y),
          "l"(*(unsigned long long*)&z));
    return r;
}

// ---------------------------------------------------------------------------
// Main kernel.
// Thread (d = tid&63, ig = tid>>6) owns:
//   - all 8 batches as 4 float2 b-pairs
//   - 8 consecutive i's: i0 + ig*8 + g, g in [0,8)
// Accumulators: acc[8 g][4 bp] float2 (64 regs), alpha folded into FMA.
// Smem: hs[JT][4 bp][64 d] float2 (128KB), bpk_s[8][JT] u32, a2s[8][64] float2.
// k = bucket is warp-uniform (lanes differ only in d) -> broadcast bpk load,
// conflict-free stride-8B alpha/h LDS.
// ---------------------------------------------------------------------------
__global__ void __launch_bounds__(TPB) dist_mix_kernel(
    const float* __restrict__ h,
    const float* __restrict__ alpha,
    float* __restrict__ out)
{
    extern __shared__ char smem[];
    float2* hs             = (float2*)smem;                              // [JT*4*64]
    unsigned int* bpk_s    = (unsigned int*)(smem + JT * 4 * 64 * 8);    // [8*JT]
    float2* a2s            = (float2*)(smem + JT * 4 * 64 * 8 + 8 * JT * 4); // [512]

    const int tid = threadIdx.x;
    const int d   = tid & 63;
    const int ig  = tid >> 6;
    const int i0  = blockIdx.x * IT;

    // Stage alpha, duplicated into both float2 halves (so FFMA2 needs no pack).
#pragma unroll
    for (int t = tid; t < 512; t += TPB) {
        float a = alpha[t];
        a2s[t] = make_float2(a, a);
    }

    float2 acc[8][4];
#pragma unroll
    for (int g = 0; g < 8; ++g)
#pragma unroll
        for (int p = 0; p < 4; ++p) acc[g][p] = make_float2(0.f, 0.f);

    for (int jt = 0; jt < NN; jt += JT) {
        __syncthreads();   // also covers alpha staging on first iteration

        // Stage packed buckets: rows ii = i0/4 .. i0/4+7, JT columns.
#pragma unroll
        for (int t = tid; t < 8 * JT; t += TPB) {
            int jj = t & (JT - 1);
            int ii = t >> 6;     // JT == 64
            bpk_s[t] = g_bpk[(i0 / 4 + ii) * NN + jt + jj];
        }

        // Stage h tile as [j][bpair][d] float2. 16 quad-tasks per thread.
#pragma unroll 4
        for (int t = tid; t < JT * 64; t += TPB) {
            int dq = t & 15;
            int bp = (t >> 4) & 3;
            int jp = t >> 6;
            const float4 va = *(const float4*)(h + ((size_t)(2 * bp + 0) * NN + jt + jp) * DD + dq * 4);
            const float4 vb = *(const float4*)(h + ((size_t)(2 * bp + 1) * NN + jt + jp) * DD + dq * 4);
            float4* dst = (float4*)(hs + ((jp * 4 + bp) * 64 + dq * 4));
            dst[0] = make_float4(va.x, vb.x, va.y, vb.y);
            dst[1] = make_float4(va.z, vb.z, va.w, vb.w);
        }
        __syncthreads();

        const unsigned int* brow0 = &bpk_s[(ig * 2 + 0) * JT];
        const unsigned int* brow1 = &bpk_s[(ig * 2 + 1) * JT];

#pragma unroll 2
        for (int jj = 0; jj < JT; ++jj) {
            const float2 h0 = hs[(jj * 4 + 0) * 64 + d];
            const float2 h1 = hs[(jj * 4 + 1) * 64 + d];
            const float2 h2 = hs[(jj * 4 + 2) * 64 + d];
            const float2 h3 = hs[(jj * 4 + 3) * 64 + d];
            const unsigned int w0 = brow0[jj];   // warp-uniform broadcast
            const unsigned int w1 = brow1[jj];

#pragma unroll
            for (int g = 0; g < 4; ++g) {
                unsigned int k = (w0 >> (8 * g)) & 7u;
                float2 a = a2s[k * 64 + d];      // conflict-free LDS.64
                acc[g][0] = ffma2(h0, a, acc[g][0]);
                acc[g][1] = ffma2(h1, a, acc[g][1]);
                acc[g][2] = ffma2(h2, a, acc[g][2]);
                acc[g][3] = ffma2(h3, a, acc[g][3]);
            }
#pragma unroll
            for (int g = 0; g < 4; ++g) {
                unsigned int k = (w1 >> (8 * g)) & 7u;
                float2 a = a2s[k * 64 + d];
                acc[4 + g][0] = ffma2(h0, a, acc[4 + g][0]);
                acc[4 + g][1] = ffma2(h1, a, acc[4 + g][1]);
                acc[4 + g][2] = ffma2(h2, a, acc[4 + g][2]);
                acc[4 + g][3] = ffma2(h3, a, acc[4 + g][3]);
            }
        }
    }

    // Epilogue: out[b][i][d], coalesced over d-lanes.
#pragma unroll
    for (int g = 0; g < 8; ++g) {
        int i = i0 + ig * 8 + g;
#pragma unroll
        for (int p = 0; p < 4; ++p) {
            out[((size_t)(2 * p + 0) * NN + i) * DD + d] = acc[g][p].x;
            out[((size_t)(2 * p + 1) * NN + i) * DD + d] = acc[g][p].y;
        }
    }
}

// ---------------------------------------------------------------------------
extern "C" void kernel_launch(void* const* d_in, const int* in_sizes, int n_in,
                              void* d_out, int out_size) {
    // Identify inputs by element count (robust to ordering).
    const float* h = nullptr;
    const void*  spd = nullptr;
    const float* alpha = nullptr;
    for (int i = 0; i < n_in; ++i) {
        if (in_sizes[i] == BB * NN * DD)      h     = (const float*)d_in[i];
        else if (in_sizes[i] == NN * NN)      spd   = (const void*)d_in[i];
        else if (in_sizes[i] == 8 * DD)       alpha = (const float*)d_in[i];
    }

    // 1) spd -> packed bucket words (reads spd once; 128MB -> 16MB).
    convert_spd_kernel<<<(NN / 4) * NN / 256, 256>>>((const unsigned int*)spd);

    // 2) main mix kernel: 128 blocks x 256 threads, 137,216 B dynamic smem.
    const int smem_bytes = JT * 4 * 64 * 8 + 8 * JT * 4 + 512 * 8;
    cudaFuncSetAttribute(dist_mix_kernel,
                         cudaFuncAttributeMaxDynamicSharedMemorySize, smem_bytes);
    dist_mix_kernel<<<NN / IT, TPB, smem_bytes>>>(h, alpha, (float*)d_out);
}

// round 7
// speedup vs baseline: 1.1171x; 1.1171x over previous
#include <cuda_runtime.h>

// DistTokenMix: out[b,i,d] = sum_j h[b,j,d] * alpha[spd[i,j], d]
// B=8, N=4096, D=64, NUM_BUCKETS=8

#define NN 4096
#define BB 8
#define DD 64
#define IT 64          // i-tile per block
#define JT 64          // j-tile staged in smem
#define TPB 256        // 32 d-pair lanes x 8 i-groups (warp == i-group)
#define NSPLIT 2       // j-range splits (grid.y)

// Packed buckets: word[ii*NN + j] holds buckets for i = 4*ii..4*ii+3 at column j.
__device__ unsigned int g_bpk[(NN / 4) * NN];
// Per-split partial outputs (combined by a final kernel; deterministic).
__device__ float g_part[NSPLIT][(size_t)BB * NN * DD];

// ---------------------------------------------------------------------------
// Convert spd (int64 OR int32, detected at runtime) -> packed u32 buckets.
// ---------------------------------------------------------------------------
__global__ void __launch_bounds__(256) convert_spd_kernel(const unsigned int* __restrict__ spd_raw) {
    __shared__ int s_is64;
    if (threadIdx.x == 0) {
        unsigned int orv = 0;
#pragma unroll
        for (int t = 1; t < 64; t += 2) orv |= spd_raw[t];
        s_is64 = (orv == 0u) ? 1 : 0;     // int64: odd words of small values are 0
    }
    __syncthreads();
    const bool is64 = (s_is64 != 0);

    int idx = blockIdx.x * blockDim.x + threadIdx.x;   // over (NN/4)*NN
    int j  = idx & (NN - 1);
    int ii = idx >> 12;                                 // NN = 4096 = 2^12
    unsigned int w = 0;
#pragma unroll
    for (int c = 0; c < 4; ++c) {
        long long off = (long long)(4 * ii + c) * NN + j;
        unsigned int v = is64 ? spd_raw[off * 2] : spd_raw[off];
        w |= (v & 7u) << (8 * c);
    }
    g_bpk[idx] = w;
}

// ---------------------------------------------------------------------------
// Packed fp32x2 FMA (FFMA2) — PTX-only on sm_103a; pairs adjacent d channels.
// ---------------------------------------------------------------------------
__device__ __forceinline__ float2 ffma2(float2 x, float2 y, float2 z) {
    float2 r;
    asm("fma.rn.f32x2 %0, %1, %2, %3;"
        : "=l"(*(unsigned long long*)&r)
        : "l"(*(unsigned long long*)&x),
          "l"(*(unsigned long long*)&y),
          "l"(*(unsigned long long*)&z));
    return r;
}

// ---------------------------------------------------------------------------
// Main kernel. Thread (dp = tid&31 -> d pair 2dp..2dp+1, ig = tid>>5 = warp)
// owns 8 batches x 8 i's (i = i0 + 8*ig + g). Accumulators acc[8 g][8 b]
// float2-over-d = 128 floats (spill-free via __launch_bounds__(256,1)).
// Smem: hs[JT][8 b][32 dp] float2 (128KB, natural d-major layout),
//       bpk_s[16][JT] u32, a2[8 k][32 dp] float2 (no duplication).
// Bucket k is warp-uniform (lanes differ only in dp) -> broadcast word load,
// conflict-free stride-8B alpha/h LDS.64.
// ---------------------------------------------------------------------------
__global__ void __launch_bounds__(TPB, 1) dist_mix_kernel(
    const float* __restrict__ h,
    const float* __restrict__ alpha)
{
    extern __shared__ char smem[];
    float2* hs          = (float2*)smem;                                  // [JT*8*32]
    unsigned int* bpk_s = (unsigned int*)(smem + JT * 8 * 32 * 8);        // [16*JT]
    float2* a2          = (float2*)(smem + JT * 8 * 32 * 8 + 16 * JT * 4);// [8*32]

    const int tid = threadIdx.x;
    const int dp  = tid & 31;        // d pair index
    const int ig  = tid >> 5;        // == warp id, 0..7
    const int i0  = blockIdx.x * IT;
    const int split = blockIdx.y;
    const int j_begin = split * (NN / NSPLIT);
    const int j_end   = j_begin + (NN / NSPLIT);

    // Stage alpha as natural float2-over-d: a2[k*32+dp] = (alpha[k][2dp], alpha[k][2dp+1])
    if (tid < 256) a2[tid] = ((const float2*)alpha)[tid];

    float2 acc[8][8];
#pragma unroll
    for (int g = 0; g < 8; ++g)
#pragma unroll
        for (int b = 0; b < 8; ++b) acc[g][b] = make_float2(0.f, 0.f);

    for (int jt = j_begin; jt < j_end; jt += JT) {
        __syncthreads();   // also covers alpha staging on first iteration

        // Stage packed buckets: 16 ii-rows x JT columns.
#pragma unroll
        for (int t = tid; t < 16 * JT; t += TPB) {
            int jj = t & (JT - 1);
            int ii = t >> 6;                 // JT == 64
            bpk_s[t] = g_bpk[(i0 / 4 + ii) * NN + jt + jj];
        }

        // Stage h tile as hs[j][b][d] (float4 over d). 32 tasks per thread.
#pragma unroll 8
        for (int t = tid; t < JT * 8 * 16; t += TPB) {
            int dq = t & 15;
            int b  = (t >> 4) & 7;
            int jp = t >> 7;
            ((float4*)hs)[(jp * 8 + b) * 16 + dq] =
                *(const float4*)(h + ((size_t)b * NN + jt + jp) * DD + dq * 4);
        }
        __syncthreads();

        const unsigned int* br0 = &bpk_s[(2 * ig + 0) * JT];
        const unsigned int* br1 = &bpk_s[(2 * ig + 1) * JT];

#pragma unroll 2
        for (int jj = 0; jj < JT; ++jj) {
            float2 hv[8];
#pragma unroll
            for (int b = 0; b < 8; ++b) hv[b] = hs[(jj * 8 + b) * 32 + dp];
            const unsigned int w0 = br0[jj];   // warp-uniform broadcast
            const unsigned int w1 = br1[jj];

#pragma unroll
            for (int g = 0; g < 4; ++g) {
                unsigned int k = (w0 >> (8 * g)) & 7u;
                float2 a = a2[k * 32 + dp];    // conflict-free LDS.64
#pragma unroll
                for (int b = 0; b < 8; ++b) acc[g][b] = ffma2(hv[b], a, acc[g][b]);
            }
#pragma unroll
            for (int g = 0; g < 4; ++g) {
                unsigned int k = (w1 >> (8 * g)) & 7u;
                float2 a = a2[k * 32 + dp];
#pragma unroll
                for (int b = 0; b < 8; ++b) acc[4 + g][b] = ffma2(hv[b], a, acc[4 + g][b]);
            }
        }
    }

    // Epilogue: partial[b][i][d], coalesced float2 over d lanes.
    // Word br0 byte g -> i = i0+8ig+g ; word br1 byte g -> i = i0+8ig+4+g.
    float* part = g_part[split];
#pragma unroll
    for (int g = 0; g < 8; ++g) {
        int i = i0 + ig * 8 + ((g < 4) ? g : (4 + (g - 4)));   // == i0+8ig+g
#pragma unroll
        for (int b = 0; b < 8; ++b)
            *(float2*)(part + ((size_t)b * NN + i) * DD + 2 * dp) = acc[g][b];
    }
}

// ---------------------------------------------------------------------------
// Combine partials into d_out (deterministic sum; float4 vectorized).
// ---------------------------------------------------------------------------
__global__ void __launch_bounds__(256) combine_kernel(float4* __restrict__ out) {
    size_t t = (size_t)blockIdx.x * blockDim.x + threadIdx.x;  // over 2M/4
    const float4 p0 = ((const float4*)g_part[0])[t];
    const float4 p1 = ((const float4*)g_part[1])[t];
    out[t] = make_float4(p0.x + p1.x, p0.y + p1.y, p0.z + p1.z, p0.w + p1.w);
}

// ---------------------------------------------------------------------------
extern "C" void kernel_launch(void* const* d_in, const int* in_sizes, int n_in,
                              void* d_out, int out_size) {
    const float* h = nullptr;
    const void*  spd = nullptr;
    const float* alpha = nullptr;
    for (int i = 0; i < n_in; ++i) {
        if (in_sizes[i] == BB * NN * DD)      h     = (const float*)d_in[i];
        else if (in_sizes[i] == NN * NN)      spd   = (const void*)d_in[i];
        else if (in_sizes[i] == 8 * DD)       alpha = (const float*)d_in[i];
    }

    // 1) spd -> packed bucket words (128MB -> 16MB, read once).
    convert_spd_kernel<<<(NN / 4) * NN / 256, 256>>>((const unsigned int*)spd);

    // 2) main mix: grid (64 i-tiles, 2 j-splits) = 128 blocks, 137,216 B smem.
    const int smem_bytes = JT * 8 * 32 * 8 + 16 * JT * 4 + 8 * 32 * 8;
    cudaFuncSetAttribute(dist_mix_kernel,
                         cudaFuncAttributeMaxDynamicSharedMemorySize, smem_bytes);
    dist_mix_kernel<<<dim3(NN / IT, NSPLIT), TPB, smem_bytes>>>(h, alpha);

    // 3) combine j-split partials into the output.
    combine_kernel<<<(BB * NN * DD / 4) / 256, 256>>>((float4*)d_out);
}

// round 8
// speedup vs baseline: 1.2636x; 1.1311x over previous
#include <cuda_runtime.h>

// DistTokenMix: out[b,i,d] = sum_j h[b,j,d] * alpha[spd[i,j], d]
// B=8, N=4096, D=64, NUM_BUCKETS=8

#define NN 4096
#define BB 8
#define DD 64
#define IT 64          // i-tile per block
#define JT 64          // j-tile staged in smem
#define TPB 256        // 32 d-pair lanes x 8 i-groups (warp == i-group)
#define NSPLIT 2       // j-range splits (grid.y)

// Packed buckets: word[ii*NN + j] holds buckets for i = 4*ii..4*ii+3 at column j.
__device__ unsigned int g_bpk[(NN / 4) * NN];
// Per-split partial outputs (combined by a final kernel; deterministic).
__device__ float g_part[NSPLIT][(size_t)BB * NN * DD];

// ---------------------------------------------------------------------------
// Convert spd (int64 OR int32, detected at runtime) -> packed u32 buckets.
// ---------------------------------------------------------------------------
__global__ void __launch_bounds__(256) convert_spd_kernel(const unsigned int* __restrict__ spd_raw) {
    __shared__ int s_is64;
    if (threadIdx.x == 0) {
        unsigned int orv = 0;
#pragma unroll
        for (int t = 1; t < 64; t += 2) orv |= spd_raw[t];
        s_is64 = (orv == 0u) ? 1 : 0;     // int64: odd words of small values are 0
    }
    __syncthreads();
    const bool is64 = (s_is64 != 0);

    int idx = blockIdx.x * blockDim.x + threadIdx.x;   // over (NN/4)*NN
    int j  = idx & (NN - 1);
    int ii = idx >> 12;                                 // NN = 4096 = 2^12
    unsigned int w = 0;
#pragma unroll
    for (int c = 0; c < 4; ++c) {
        long long off = (long long)(4 * ii + c) * NN + j;
        unsigned int v = is64 ? spd_raw[off * 2] : spd_raw[off];
        w |= (v & 7u) << (8 * c);
    }
    g_bpk[idx] = w;
}

// ---------------------------------------------------------------------------
// Packed fp32x2 FMA (FFMA2) — PTX-only on sm_103a; pairs adjacent d channels.
// ---------------------------------------------------------------------------
__device__ __forceinline__ float2 ffma2(float2 x, float2 y, float2 z) {
    float2 r;
    asm("fma.rn.f32x2 %0, %1, %2, %3;"
        : "=l"(*(unsigned long long*)&r)
        : "l"(*(unsigned long long*)&x),
          "l"(*(unsigned long long*)&y),
          "l"(*(unsigned long long*)&z));
    return r;
}

// ---------------------------------------------------------------------------
// Main kernel. Thread (dp = tid&31 -> d pair 2dp..2dp+1, ig = tid>>5 = warp)
// owns 8 batches x 8 i's (i = i0 + 8*ig + g). acc[8 g][8 b] float2 = 128 regs.
// Single CTA/SM (256 thr) -> 256-reg budget; the headroom funds a 1-deep
// software pipeline: bucket words, h vectors AND bucket-resolved alphas for
// jj+1 are loaded at the top of iteration jj, so the 29-cyc LDS latency and
// the word->k->alpha chain are covered by the 64 FFMA2s of the current jj.
// Smem: hs[JT][8 b][32 dp] float2 (128KB), bpk_s[8 ig][JT][2] u32 (word pair
// per jj fused into one broadcast LDS.64), a2[8 k][32 dp] float2.
// ---------------------------------------------------------------------------
__global__ void __launch_bounds__(TPB, 1) dist_mix_kernel(
    const float* __restrict__ h,
    const float* __restrict__ alpha)
{
    extern __shared__ char smem[];
    float2* hs          = (float2*)smem;                                  // [JT*8*32]
    unsigned int* bpk_s = (unsigned int*)(smem + JT * 8 * 32 * 8);        // [8*JT*2]
    float2* a2          = (float2*)(smem + JT * 8 * 32 * 8 + 8 * JT * 2 * 4);// [8*32]

    const int tid = threadIdx.x;
    const int dp  = tid & 31;        // d pair index
    const int ig  = tid >> 5;        // == warp id, 0..7
    const int i0  = blockIdx.x * IT;
    const int split = blockIdx.y;
    const int j_begin = split * (NN / NSPLIT);
    const int j_end   = j_begin + (NN / NSPLIT);

    // Stage alpha as natural float2-over-d: a2[k*32+dp] = (alpha[k][2dp], alpha[k][2dp+1])
    if (tid < 256) a2[tid] = ((const float2*)alpha)[tid];

    float2 acc[8][8];
#pragma unroll
    for (int g = 0; g < 8; ++g)
#pragma unroll
        for (int b = 0; b < 8; ++b) acc[g][b] = make_float2(0.f, 0.f);

    for (int jt = j_begin; jt < j_end; jt += JT) {
        __syncthreads();   // also covers alpha staging on first iteration

        // Stage packed buckets, word-pair interleaved per ig:
        // bpk_s[ig*128 + jj*2 + r] = g_bpk[(i0/4 + 2*ig + r)*NN + jt + jj]
#pragma unroll
        for (int t = tid; t < 8 * JT * 2; t += TPB) {
            int igp = t >> 7;
            int e   = t & 127;
            int jj  = e >> 1;
            int r   = e & 1;
            bpk_s[t] = g_bpk[(i0 / 4 + 2 * igp + r) * NN + jt + jj];
        }

        // Stage h tile as hs[j][b][d] (float4 over d). 32 tasks per thread.
#pragma unroll 8
        for (int t = tid; t < JT * 8 * 16; t += TPB) {
            int dq = t & 15;
            int b  = (t >> 4) & 7;
            int jp = t >> 7;
            ((float4*)hs)[(jp * 8 + b) * 16 + dq] =
                *(const float4*)(h + ((size_t)b * NN + jt + jp) * DD + dq * 4);
        }
        __syncthreads();

        const uint2* br = (const uint2*)&bpk_s[ig * (JT * 2)];

        // ---- pipeline preload for jj = 0 ----
        uint2 wc = br[0];                      // broadcast LDS.64
        float2 hc[8];
#pragma unroll
        for (int b = 0; b < 8; ++b) hc[b] = hs[(0 * 8 + b) * 32 + dp];
        float2 ac[8];
#pragma unroll
        for (int g = 0; g < 4; ++g) ac[g]     = a2[((wc.x >> (8 * g)) & 7u) * 32 + dp];
#pragma unroll
        for (int g = 0; g < 4; ++g) ac[4 + g] = a2[((wc.y >> (8 * g)) & 7u) * 32 + dp];

#pragma unroll 2
        for (int jj = 0; jj < JT; ++jj) {
            // ---- prefetch jj+1 (wraps harmlessly on the last iteration) ----
            const int jn = (jj + 1) & (JT - 1);
            uint2 wn = br[jn];
            float2 hn[8];
#pragma unroll
            for (int b = 0; b < 8; ++b) hn[b] = hs[(jn * 8 + b) * 32 + dp];
            float2 an[8];
#pragma unroll
            for (int g = 0; g < 4; ++g) an[g]     = a2[((wn.x >> (8 * g)) & 7u) * 32 + dp];
#pragma unroll
            for (int g = 0; g < 4; ++g) an[4 + g] = a2[((wn.y >> (8 * g)) & 7u) * 32 + dp];

            // ---- compute with preloaded operands ----
#pragma unroll
            for (int g = 0; g < 8; ++g)
#pragma unroll
                for (int b = 0; b < 8; ++b)
                    acc[g][b] = ffma2(hc[b], ac[g], acc[g][b]);

            // ---- rotate ----
            wc = wn;
#pragma unroll
            for (int b = 0; b < 8; ++b) hc[b] = hn[b];
#pragma unroll
            for (int g = 0; g < 8; ++g) ac[g] = an[g];
        }
    }

    // Epilogue: partial[b][i][d], coalesced float2 over d lanes.
    // acc[g] corresponds to i = i0 + 8*ig + g (g<4 from word r=0, g>=4 from r=1).
    float* part = g_part[split];
#pragma unroll
    for (int g = 0; g < 8; ++g) {
        int i = i0 + ig * 8 + g;
#pragma unroll
        for (int b = 0; b < 8; ++b)
            *(float2*)(part + ((size_t)b * NN + i) * DD + 2 * dp) = acc[g][b];
    }
}

// ---------------------------------------------------------------------------
// Combine partials into d_out (deterministic sum; float4 vectorized).
// ---------------------------------------------------------------------------
__global__ void __launch_bounds__(256) combine_kernel(float4* __restrict__ out) {
    size_t t = (size_t)blockIdx.x * blockDim.x + threadIdx.x;  // over 2M/4
    const float4 p0 = ((const float4*)g_part[0])[t];
    const float4 p1 = ((const float4*)g_part[1])[t];
    out[t] = make_float4(p0.x + p1.x, p0.y + p1.y, p0.z + p1.z, p0.w + p1.w);
}

// ---------------------------------------------------------------------------
extern "C" void kernel_launch(void* const* d_in, const int* in_sizes, int n_in,
                              void* d_out, int out_size) {
    const float* h = nullptr;
    const void*  spd = nullptr;
    const float* alpha = nullptr;
    for (int i = 0; i < n_in; ++i) {
        if (in_sizes[i] == BB * NN * DD)      h     = (const float*)d_in[i];
        else if (in_sizes[i] == NN * NN)      spd   = (const void*)d_in[i];
        else if (in_sizes[i] == 8 * DD)       alpha = (const float*)d_in[i];
    }

    // 1) spd -> packed bucket words (128MB -> 16MB, read once).
    convert_spd_kernel<<<(NN / 4) * NN / 256, 256>>>((const unsigned int*)spd);

    // 2) main mix: grid (64 i-tiles, 2 j-splits) = 128 blocks.
    const int smem_bytes = JT * 8 * 32 * 8 + 8 * JT * 2 * 4 + 8 * 32 * 8;
    cudaFuncSetAttribute(dist_mix_kernel,
                         cudaFuncAttributeMaxDynamicSharedMemorySize, smem_bytes);
    dist_mix_kernel<<<dim3(NN / IT, NSPLIT), TPB, smem_bytes>>>(h, alpha);

    // 3) combine j-split partials into the output.
    combine_kernel<<<(BB * NN * DD / 4) / 256, 256>>>((float4*)d_out);
}

// round 9
// speedup vs baseline: 1.2934x; 1.0236x over previous
#include <cuda_runtime.h>

// DistTokenMix: out[b,i,d] = sum_j h[b,j,d] * alpha[spd[i,j], d]
// B=8, N=4096, D=64, NUM_BUCKETS=8

#define NN 4096
#define BB 8
#define DD 64
#define IT 64          // i-tile per block
#define JT 64          // j-tile staged in smem
#define TPB 256        // 32 d-pair lanes x 8 i-groups (warp == i-group)
#define NSPLIT 2       // j-range splits (grid.y)

// Packed buckets: word[ii*NN + j] holds buckets for i = 4*ii..4*ii+3 at column j.
__device__ unsigned int g_bpk[(NN / 4) * NN];
// Per-split partial outputs (combined by a final kernel; deterministic).
__device__ float g_part[NSPLIT][(size_t)BB * NN * DD];

// ---------------------------------------------------------------------------
// Convert spd (int64 OR int32, detected at runtime) -> packed u32 buckets.
// ---------------------------------------------------------------------------
__global__ void __launch_bounds__(256) convert_spd_kernel(const unsigned int* __restrict__ spd_raw) {
    __shared__ int s_is64;
    if (threadIdx.x == 0) {
        unsigned int orv = 0;
#pragma unroll
        for (int t = 1; t < 64; t += 2) orv |= spd_raw[t];
        s_is64 = (orv == 0u) ? 1 : 0;     // int64: odd words of small values are 0
    }
    __syncthreads();
    const bool is64 = (s_is64 != 0);

    int idx = blockIdx.x * blockDim.x + threadIdx.x;   // over (NN/4)*NN
    int j  = idx & (NN - 1);
    int ii = idx >> 12;                                 // NN = 4096 = 2^12
    unsigned int w = 0;
#pragma unroll
    for (int c = 0; c < 4; ++c) {
        long long off = (long long)(4 * ii + c) * NN + j;
        unsigned int v = is64 ? spd_raw[off * 2] : spd_raw[off];
        w |= (v & 7u) << (8 * c);
    }
    g_bpk[idx] = w;
}

// ---------------------------------------------------------------------------
// Packed fp32x2 FMA (FFMA2) — PTX-only on sm_103a; pairs adjacent d channels.
// ---------------------------------------------------------------------------
__device__ __forceinline__ float2 ffma2(float2 x, float2 y, float2 z) {
    float2 r;
    asm("fma.rn.f32x2 %0, %1, %2, %3;"
        : "=l"(*(unsigned long long*)&r)
        : "l"(*(unsigned long long*)&x),
          "l"(*(unsigned long long*)&y),
          "l"(*(unsigned long long*)&z));
    return r;
}

// ---------------------------------------------------------------------------
// Main kernel. Thread (dp = tid&31 -> d pair 2dp..2dp+1, ig = tid>>5 = warp)
// owns 8 batches x 8 i's (i = i0 + 8*ig + g). acc[8 g][8 b] float2 = 128 regs.
// Single CTA/SM (256 thr) -> 256-reg budget; the headroom funds a 1-deep
// software pipeline: bucket words, h vectors AND bucket-resolved alphas for
// jj+1 are loaded at the top of iteration jj, so the 29-cyc LDS latency and
// the word->k->alpha chain are covered by the 64 FFMA2s of the current jj.
// Smem: hs[JT][8 b][32 dp] float2 (128KB), bpk_s[8 ig][JT][2] u32 (word pair
// per jj fused into one broadcast LDS.64), a2[8 k][32 dp] float2.
// ---------------------------------------------------------------------------
__global__ void __launch_bounds__(TPB, 1) dist_mix_kernel(
    const float* __restrict__ h,
    const float* __restrict__ alpha)
{
    extern __shared__ char smem[];
    float2* hs          = (float2*)smem;                                  // [JT*8*32]
    unsigned int* bpk_s = (unsigned int*)(smem + JT * 8 * 32 * 8);        // [8*JT*2]
    float2* a2          = (float2*)(smem + JT * 8 * 32 * 8 + 8 * JT * 2 * 4);// [8*32]

    const int tid = threadIdx.x;
    const int dp  = tid & 31;        // d pair index
    const int ig  = tid >> 5;        // == warp id, 0..7
    const int i0  = blockIdx.x * IT;
    const int split = blockIdx.y;
    const int j_begin = split * (NN / NSPLIT);
    const int j_end   = j_begin + (NN / NSPLIT);

    // Stage alpha as natural float2-over-d: a2[k*32+dp] = (alpha[k][2dp], alpha[k][2dp+1])
    if (tid < 256) a2[tid] = ((const float2*)alpha)[tid];

    float2 acc[8][8];
#pragma unroll
    for (int g = 0; g < 8; ++g)
#pragma unroll
        for (int b = 0; b < 8; ++b) acc[g][b] = make_float2(0.f, 0.f);

    for (int jt = j_begin; jt < j_end; jt += JT) {
        __syncthreads();   // also covers alpha staging on first iteration

        // Stage packed buckets, word-pair interleaved per ig:
        // bpk_s[ig*128 + jj*2 + r] = g_bpk[(i0/4 + 2*ig + r)*NN + jt + jj]
#pragma unroll
        for (int t = tid; t < 8 * JT * 2; t += TPB) {
            int igp = t >> 7;
            int e   = t & 127;
            int jj  = e >> 1;
            int r   = e & 1;
            bpk_s[t] = g_bpk[(i0 / 4 + 2 * igp + r) * NN + jt + jj];
        }

        // Stage h tile as hs[j][b][d] (float4 over d). 32 tasks per thread.
#pragma unroll 8
        for (int t = tid; t < JT * 8 * 16; t += TPB) {
            int dq = t & 15;
            int b  = (t >> 4) & 7;
            int jp = t >> 7;
            ((float4*)hs)[(jp * 8 + b) * 16 + dq] =
                *(const float4*)(h + ((size_t)b * NN + jt + jp) * DD + dq * 4);
        }
        __syncthreads();

        const uint2* br = (const uint2*)&bpk_s[ig * (JT * 2)];

        // ---- pipeline preload for jj = 0 ----
        uint2 wc = br[0];                      // broadcast LDS.64
        float2 hc[8];
#pragma unroll
        for (int b = 0; b < 8; ++b) hc[b] = hs[(0 * 8 + b) * 32 + dp];
        float2 ac[8];
#pragma unroll
        for (int g = 0; g < 4; ++g) ac[g]     = a2[((wc.x >> (8 * g)) & 7u) * 32 + dp];
#pragma unroll
        for (int g = 0; g < 4; ++g) ac[4 + g] = a2[((wc.y >> (8 * g)) & 7u) * 32 + dp];

#pragma unroll 2
        for (int jj = 0; jj < JT; ++jj) {
            // ---- prefetch jj+1 (wraps harmlessly on the last iteration) ----
            const int jn = (jj + 1) & (JT - 1);
            uint2 wn = br[jn];
            float2 hn[8];
#pragma unroll
            for (int b = 0; b < 8; ++b) hn[b] = hs[(jn * 8 + b) * 32 + dp];
            float2 an[8];
#pragma unroll
            for (int g = 0; g < 4; ++g) an[g]     = a2[((wn.x >> (8 * g)) & 7u) * 32 + dp];
#pragma unroll
            for (int g = 0; g < 4; ++g) an[4 + g] = a2[((wn.y >> (8 * g)) & 7u) * 32 + dp];

            // ---- compute with preloaded operands ----
#pragma unroll
            for (int g = 0; g < 8; ++g)
#pragma unroll
                for (int b = 0; b < 8; ++b)
                    acc[g][b] = ffma2(hc[b], ac[g], acc[g][b]);

            // ---- rotate ----
            wc = wn;
#pragma unroll
            for (int b = 0; b < 8; ++b) hc[b] = hn[b];
#pragma unroll
            for (int g = 0; g < 8; ++g) ac[g] = an[g];
        }
    }

    // Epilogue: partial[b][i][d], coalesced float2 over d lanes.
    // acc[g] corresponds to i = i0 + 8*ig + g (g<4 from word r=0, g>=4 from r=1).
    float* part = g_part[split];
#pragma unroll
    for (int g = 0; g < 8; ++g) {
        int i = i0 + ig * 8 + g;
#pragma unroll
        for (int b = 0; b < 8; ++b)
            *(float2*)(part + ((size_t)b * NN + i) * DD + 2 * dp) = acc[g][b];
    }
}

// ---------------------------------------------------------------------------
// Combine partials into d_out (deterministic sum; float4 vectorized).
// ---------------------------------------------------------------------------
__global__ void __launch_bounds__(256) combine_kernel(float4* __restrict__ out) {
    size_t t = (size_t)blockIdx.x * blockDim.x + threadIdx.x;  // over 2M/4
    const float4 p0 = ((const float4*)g_part[0])[t];
    const float4 p1 = ((const float4*)g_part[1])[t];
    out[t] = make_float4(p0.x + p1.x, p0.y + p1.y, p0.z + p1.z, p0.w + p1.w);
}

// ---------------------------------------------------------------------------
extern "C" void kernel_launch(void* const* d_in, const int* in_sizes, int n_in,
                              void* d_out, int out_size) {
    const float* h = nullptr;
    const void*  spd = nullptr;
    const float* alpha = nullptr;
    for (int i = 0; i < n_in; ++i) {
        if (in_sizes[i] == BB * NN * DD)      h     = (const float*)d_in[i];
        else if (in_sizes[i] == NN * NN)      spd   = (const void*)d_in[i];
        else if (in_sizes[i] == 8 * DD)       alpha = (const float*)d_in[i];
    }

    // 1) spd -> packed bucket words (128MB -> 16MB, read once).
    convert_spd_kernel<<<(NN / 4) * NN / 256, 256>>>((const unsigned int*)spd);

    // 2) main mix: grid (64 i-tiles, 2 j-splits) = 128 blocks.
    const int smem_bytes = JT * 8 * 32 * 8 + 8 * JT * 2 * 4 + 8 * 32 * 8;
    cudaFuncSetAttribute(dist_mix_kernel,
                         cudaFuncAttributeMaxDynamicSharedMemorySize, smem_bytes);
    dist_mix_kernel<<<dim3(NN / IT, NSPLIT), TPB, smem_bytes>>>(h, alpha);

    // 3) combine j-split partials into the output.
    combine_kernel<<<(BB * NN * DD / 4) / 256, 256>>>((float4*)d_out);
}